// round 16
// baseline (speedup 1.0000x reference)
#include <cuda_runtime.h>
#include <cuda_bf16.h>
#include <mma.h>
#include <cstdint>

using namespace nvcuda;

#define NNODES 50000
#define NEDGES 1600000

// ---------------- scratch (static device globals; no allocation) -------------
__device__ float g_T1[(size_t)NNODES * 512];
__device__ float g_T2[(size_t)NNODES * 512];
__device__ float g_h1[(size_t)NNODES * 250];
__device__ float g_h2[(size_t)NNODES * 500];
__device__ int   g_deg[NNODES];
__device__ float g_dinv[NNODES];
__device__ float g_diag[NNODES];
__device__ int   g_off[NNODES + 1];
__device__ int   g_cursor[NNODES];
__device__ int   g_ccol[NEDGES];
__device__ float g_cw[NEDGES];
__device__ int   g_row[NEDGES];
__device__ int   g_col[NEDGES];
__device__ int   g_is64;

// ---------------- preprocessing ---------------------------------------------
__global__ void k_zero(int* __restrict__ p, int n) {
    int i = blockIdx.x * blockDim.x + threadIdx.x;
    if (i < n) p[i] = 0;
}

// Detect whether edge_index buffer is int64 or int32 (verified R14).
__global__ void k_detect(const long long* __restrict__ ei) {
    if (threadIdx.x == 0 && blockIdx.x == 0) {
        int ok = 1;
        for (int i = 0; i < 64; i++) {
            long long v = ei[i];
            if (v < 0 || v >= NNODES) { ok = 0; break; }
        }
        g_is64 = ok;
    }
}

__global__ void k_deg(const void* __restrict__ eiv, int* __restrict__ row,
                      int* __restrict__ col, int* __restrict__ deg) {
    int e = blockIdx.x * blockDim.x + threadIdx.x;
    if (e < NEDGES) {
        int c, r;
        if (g_is64) {
            const long long* ei = (const long long*)eiv;
            c = (int)ei[e];
            r = (int)ei[NEDGES + e];
        } else {
            const int* ei = (const int*)eiv;
            c = ei[e];
            r = ei[NEDGES + e];
        }
        if ((unsigned)c >= NNODES) c = 0;
        if ((unsigned)r >= NNODES) r = 0;
        row[e] = r;
        col[e] = c;
        atomicAdd(&deg[r], 1);
    }
}

__global__ void k_dinv(const int* __restrict__ deg, float* __restrict__ dinv,
                       float* __restrict__ diag) {
    int v = blockIdx.x * blockDim.x + threadIdx.x;
    if (v < NNODES) {
        int d = deg[v];
        dinv[v] = (d > 0) ? rsqrtf((float)d) : 0.0f;
        diag[v] = (d > 0) ? 0.0f : -1.0f;
    }
}

__global__ void k_scan(const int* __restrict__ deg, int* __restrict__ off,
                       int* __restrict__ cursor) {
    __shared__ int sh[1024];
    __shared__ int carry;
    int t = threadIdx.x;
    if (t == 0) carry = 0;
    __syncthreads();
    for (int base = 0; base < NNODES; base += 1024) {
        int i = base + t;
        int v = (i < NNODES) ? deg[i] : 0;
        sh[t] = v;
        __syncthreads();
        for (int ofs = 1; ofs < 1024; ofs <<= 1) {
            int x = (t >= ofs) ? sh[t - ofs] : 0;
            __syncthreads();
            sh[t] += x;
            __syncthreads();
        }
        int excl = carry + sh[t] - v;
        if (i < NNODES) { off[i] = excl; cursor[i] = excl; }
        __syncthreads();
        if (t == 1023) carry += sh[1023];
        __syncthreads();
    }
    if (t == 0) off[NNODES] = carry;
}

__global__ void k_csr(const int* __restrict__ row, const int* __restrict__ col,
                      const float* __restrict__ dinv, int* __restrict__ cursor,
                      int* __restrict__ ccol, float* __restrict__ cw) {
    int e = blockIdx.x * blockDim.x + threadIdx.x;
    if (e < NEDGES) {
        int r = row[e], c = col[e];
        int pos = atomicAdd(&cursor[r], 1);
        ccol[pos] = c;
        cw[pos] = -dinv[r] * dinv[c];
    }
}

// ---------------- Lhat aggregation (float2-vectorized CSR gather) -------------
// mode 0: out = agg(h) + diag*h
// mode 1: out = 2*(agg(h) + diag*h) - t0
__global__ void k_lhat2(const float2* __restrict__ h, const float2* __restrict__ t0,
                        const int* __restrict__ off, const int* __restrict__ ccol,
                        const float* __restrict__ cw, const float* __restrict__ diag,
                        float2* __restrict__ out, int F2, int mode) {
    int v = blockIdx.x;
    int f = blockIdx.y * blockDim.x + threadIdx.x;
    if (f >= F2) return;
    int e0 = off[v], e1 = off[v + 1];
    float ax = 0.0f, ay = 0.0f;
    int e = e0;
    for (; e + 4 <= e1; e += 4) {
        int c0 = ccol[e + 0], c1 = ccol[e + 1], c2 = ccol[e + 2], c3 = ccol[e + 3];
        float w0 = cw[e + 0], w1 = cw[e + 1], w2 = cw[e + 2], w3 = cw[e + 3];
        float2 h0 = h[(size_t)c0 * F2 + f];
        float2 h1 = h[(size_t)c1 * F2 + f];
        float2 h2 = h[(size_t)c2 * F2 + f];
        float2 h3 = h[(size_t)c3 * F2 + f];
        ax += w0 * h0.x + w1 * h1.x + w2 * h2.x + w3 * h3.x;
        ay += w0 * h0.y + w1 * h1.y + w2 * h2.y + w3 * h3.y;
    }
    for (; e < e1; ++e) {
        int c = ccol[e];
        float w = cw[e];
        float2 hv = h[(size_t)c * F2 + f];
        ax += w * hv.x;
        ay += w * hv.y;
    }
    float dg = diag[v];
    float2 hv = h[(size_t)v * F2 + f];
    ax += dg * hv.x;
    ay += dg * hv.y;
    if (mode) {
        float2 tv = t0[(size_t)v * F2 + f];
        ax = 2.0f * ax - tv.x;
        ay = 2.0f * ay - tv.y;
    }
    out[(size_t)v * F2 + f] = make_float2(ax, ay);
}

// ---------------- fused 3-term bf16-split tensor-core GEMM --------------------
// out[M,N] = relu(sum_k Tk@W[k] + bias), fp32 in/out.
// Each fp32 a is split a = hi + lo (both bf16); product approximated by
// hi*hi + hi*lo + lo*hi with fp32 accumulate -> rel err ~2^-16.
#define GBM 128
#define GBN 64
#define GBK 16
#define A_LD 32   // bf16 elems per smem row (>=16, mult of 16 for 32B-aligned rows)
#define B_LD 80   // bf16 elems per smem row (>=64, mult of 16)

__global__ __launch_bounds__(256) void k_wmma3(
    const float* __restrict__ A0, const float* __restrict__ A1,
    const float* __restrict__ A2, const float* __restrict__ W,
    const float* __restrict__ bias, float* __restrict__ out,
    int M, int N, int K) {
    __shared__ union {
        struct {
            __nv_bfloat16 a_hi[GBM][A_LD];
            __nv_bfloat16 a_lo[GBM][A_LD];
            __nv_bfloat16 b_hi[GBK][B_LD];
            __nv_bfloat16 b_lo[GBK][B_LD];
        } tiles;                       // 16KB + 5KB
        float c[GBM][GBN];             // 32KB
    } sm;

    int bm = blockIdx.y * GBM, bn = blockIdx.x * GBN;
    int t = threadIdx.x;
    int warp = t >> 5;
    int warp_m = warp & 3;   // 4 warps along M, 32 rows each
    int warp_n = warp >> 2;  // 2 warps along N, 32 cols each

    wmma::fragment<wmma::accumulator, 16, 16, 16, float> acc[2][2];
#pragma unroll
    for (int i = 0; i < 2; i++)
#pragma unroll
        for (int j = 0; j < 2; j++) wmma::fill_fragment(acc[i][j], 0.0f);

    const float* Aptr[3] = {A0, A1, A2};
    int kTiles = (K + GBK - 1) / GBK;

    for (int kk = 0; kk < 3; ++kk) {
        const float* A = Aptr[kk];
        const float* B = W + (size_t)kk * K * N;
        for (int kt = 0; kt < kTiles; ++kt) {
            int k0 = kt * GBK;
            // ---- load & split A tile: 128x16, 8 elems/thread ----
#pragma unroll
            for (int i = 0; i < 8; i++) {
                int idx = i * 256 + t;
                int m = idx >> 4, kc = idx & 15;
                int gm = bm + m, gk = k0 + kc;
                float v = (gm < M && gk < K) ? A[(size_t)gm * K + gk] : 0.0f;
                __nv_bfloat16 hi = __float2bfloat16(v);
                float lo = v - __bfloat162float(hi);
                sm.tiles.a_hi[m][kc] = hi;
                sm.tiles.a_lo[m][kc] = __float2bfloat16(lo);
            }
            // ---- load & split B tile: 16x64, 4 elems/thread ----
#pragma unroll
            for (int i = 0; i < 4; i++) {
                int idx = i * 256 + t;
                int kr = idx >> 6, n = idx & 63;
                int gk = k0 + kr, gn = bn + n;
                float v = (gk < K && gn < N) ? B[(size_t)gk * N + gn] : 0.0f;
                __nv_bfloat16 hi = __float2bfloat16(v);
                float lo = v - __bfloat162float(hi);
                sm.tiles.b_hi[kr][n] = hi;
                sm.tiles.b_lo[kr][n] = __float2bfloat16(lo);
            }
            __syncthreads();

            wmma::fragment<wmma::matrix_a, 16, 16, 16, __nv_bfloat16, wmma::row_major> a_hi[2], a_lo[2];
            wmma::fragment<wmma::matrix_b, 16, 16, 16, __nv_bfloat16, wmma::row_major> b_hi[2], b_lo[2];
#pragma unroll
            for (int i = 0; i < 2; i++) {
                int rowb = warp_m * 32 + i * 16;
                wmma::load_matrix_sync(a_hi[i], &sm.tiles.a_hi[rowb][0], A_LD);
                wmma::load_matrix_sync(a_lo[i], &sm.tiles.a_lo[rowb][0], A_LD);
            }
#pragma unroll
            for (int j = 0; j < 2; j++) {
                int colb = warp_n * 32 + j * 16;
                wmma::load_matrix_sync(b_hi[j], &sm.tiles.b_hi[0][colb], B_LD);
                wmma::load_matrix_sync(b_lo[j], &sm.tiles.b_lo[0][colb], B_LD);
            }
#pragma unroll
            for (int i = 0; i < 2; i++)
#pragma unroll
                for (int j = 0; j < 2; j++) {
                    wmma::mma_sync(acc[i][j], a_hi[i], b_hi[j], acc[i][j]);
                    wmma::mma_sync(acc[i][j], a_hi[i], b_lo[j], acc[i][j]);
                    wmma::mma_sync(acc[i][j], a_lo[i], b_hi[j], acc[i][j]);
                }
            __syncthreads();
        }
    }

    // ---- epilogue: stage C in smem, apply bias+relu, coalesced store ----
#pragma unroll
    for (int i = 0; i < 2; i++)
#pragma unroll
        for (int j = 0; j < 2; j++) {
            int rowb = warp_m * 32 + i * 16;
            int colb = warp_n * 32 + j * 16;
            wmma::store_matrix_sync(&sm.c[rowb][colb], acc[i][j], GBN, wmma::mem_row_major);
        }
    __syncthreads();
#pragma unroll
    for (int i = 0; i < 32; i++) {
        int idx = i * 256 + t;
        int m = idx >> 6, n = idx & 63;
        int gm = bm + m, gn = bn + n;
        if (gm < M && gn < N) {
            float v = sm.c[m][n] + bias[gn];
            out[(size_t)gm * N + gn] = fmaxf(v, 0.0f);
        }
    }
}

// ---------------- launch ------------------------------------------------------
static inline int cdiv(int a, int b) { return (a + b - 1) / b; }

extern "C" void kernel_launch(void* const* d_in, const int* in_sizes, int n_in,
                              void* d_out, int out_size) {
    const float* x  = (const float*)d_in[0];
    const void*  ei = d_in[1];               // int32 or int64 — detected on device
    const float* w1 = (const float*)d_in[2];
    const float* b1 = (const float*)d_in[3];
    const float* w2 = (const float*)d_in[4];
    const float* b2 = (const float*)d_in[5];
    const float* w3 = (const float*)d_in[6];
    const float* b3 = (const float*)d_in[7];
    float* out = (float*)d_out;

    float *T1, *T2, *h1, *h2, *dinv, *diag, *cw;
    int *row, *col, *deg, *off, *cursor, *ccol;
    cudaGetSymbolAddress((void**)&T1, g_T1);
    cudaGetSymbolAddress((void**)&T2, g_T2);
    cudaGetSymbolAddress((void**)&h1, g_h1);
    cudaGetSymbolAddress((void**)&h2, g_h2);
    cudaGetSymbolAddress((void**)&row, g_row);
    cudaGetSymbolAddress((void**)&col, g_col);
    cudaGetSymbolAddress((void**)&deg, g_deg);
    cudaGetSymbolAddress((void**)&dinv, g_dinv);
    cudaGetSymbolAddress((void**)&diag, g_diag);
    cudaGetSymbolAddress((void**)&off, g_off);
    cudaGetSymbolAddress((void**)&cursor, g_cursor);
    cudaGetSymbolAddress((void**)&ccol, g_ccol);
    cudaGetSymbolAddress((void**)&cw, g_cw);

    const int M = NNODES;

    // ---- preprocessing (verified R14) ----
    k_zero<<<cdiv(NNODES, 256), 256>>>(deg, NNODES);
    k_detect<<<1, 32>>>((const long long*)ei);
    k_deg<<<cdiv(NEDGES, 256), 256>>>(ei, row, col, deg);
    k_dinv<<<cdiv(NNODES, 256), 256>>>(deg, dinv, diag);
    k_scan<<<1, 1024>>>(deg, off, cursor);
    k_csr<<<cdiv(NEDGES, 256), 256>>>(row, col, dinv, cursor, ccol, cw);

    // ---- layer 1: F=512 -> 250 ----
    {
        int F = 512, N = 250, K = 512, F2 = F / 2;
        dim3 lg(M, cdiv(F2, 128));
        k_lhat2<<<lg, 128>>>((const float2*)x, nullptr, off, ccol, cw, diag,
                             (float2*)T1, F2, 0);
        k_lhat2<<<lg, 128>>>((const float2*)T1, (const float2*)x, off, ccol, cw, diag,
                             (float2*)T2, F2, 1);
        dim3 gg(cdiv(N, GBN), cdiv(M, GBM));
        k_wmma3<<<gg, 256>>>(x, T1, T2, w1, b1, h1, M, N, K);
    }
    // ---- layer 2: F=250 -> 500 ----
    {
        int F = 250, N = 500, K = 250, F2 = F / 2;
        dim3 lg(M, cdiv(F2, 128));
        k_lhat2<<<lg, 128>>>((const float2*)h1, nullptr, off, ccol, cw, diag,
                             (float2*)T1, F2, 0);
        k_lhat2<<<lg, 128>>>((const float2*)T1, (const float2*)h1, off, ccol, cw, diag,
                             (float2*)T2, F2, 1);
        dim3 gg(cdiv(N, GBN), cdiv(M, GBM));
        k_wmma3<<<gg, 256>>>(h1, T1, T2, w2, b2, h2, M, N, K);
    }
    // ---- layer 3: F=500 -> 1000 ----
    {
        int F = 500, N = 1000, K = 500, F2 = F / 2;
        dim3 lg(M, cdiv(F2, 128));
        k_lhat2<<<lg, 128>>>((const float2*)h2, nullptr, off, ccol, cw, diag,
                             (float2*)T1, F2, 0);
        k_lhat2<<<lg, 128>>>((const float2*)T1, (const float2*)h2, off, ccol, cw, diag,
                             (float2*)T2, F2, 1);
        dim3 gg(cdiv(N, GBN), cdiv(M, GBM));
        k_wmma3<<<gg, 256>>>(h2, T1, T2, w3, b3, out, M, N, K);
    }
}

// round 17
// speedup vs baseline: 2.4582x; 2.4582x over previous
#include <cuda_runtime.h>
#include <cuda_bf16.h>
#include <cstdint>

#define NNODES 50000
#define NEDGES 1600000

// ---------------- scratch (static device globals; no allocation) -------------
__device__ float g_T1[(size_t)NNODES * 512];
__device__ float g_T2[(size_t)NNODES * 512];
__device__ float g_h1[(size_t)NNODES * 250];
__device__ float g_h2[(size_t)NNODES * 500];
__device__ int   g_deg[NNODES];
__device__ float g_dinv[NNODES];
__device__ float g_diag[NNODES];
__device__ int   g_off[NNODES + 1];
__device__ int   g_cursor[NNODES];
__device__ int   g_ccol[NEDGES];
__device__ float g_cw[NEDGES];
__device__ int   g_row[NEDGES];
__device__ int   g_col[NEDGES];
__device__ int   g_is64;

// ---------------- preprocessing ---------------------------------------------
__global__ void k_zero(int* __restrict__ p, int n) {
    int i = blockIdx.x * blockDim.x + threadIdx.x;
    if (i < n) p[i] = 0;
}

// Detect whether edge_index buffer is int64 or int32 (verified R14).
__global__ void k_detect(const long long* __restrict__ ei) {
    if (threadIdx.x == 0 && blockIdx.x == 0) {
        int ok = 1;
        for (int i = 0; i < 64; i++) {
            long long v = ei[i];
            if (v < 0 || v >= NNODES) { ok = 0; break; }
        }
        g_is64 = ok;
    }
}

__global__ void k_deg(const void* __restrict__ eiv, int* __restrict__ row,
                      int* __restrict__ col, int* __restrict__ deg) {
    int e = blockIdx.x * blockDim.x + threadIdx.x;
    if (e < NEDGES) {
        int c, r;
        if (g_is64) {
            const long long* ei = (const long long*)eiv;
            c = (int)ei[e];
            r = (int)ei[NEDGES + e];
        } else {
            const int* ei = (const int*)eiv;
            c = ei[e];
            r = ei[NEDGES + e];
        }
        if ((unsigned)c >= NNODES) c = 0;
        if ((unsigned)r >= NNODES) r = 0;
        row[e] = r;
        col[e] = c;
        atomicAdd(&deg[r], 1);
    }
}

__global__ void k_dinv(const int* __restrict__ deg, float* __restrict__ dinv,
                       float* __restrict__ diag) {
    int v = blockIdx.x * blockDim.x + threadIdx.x;
    if (v < NNODES) {
        int d = deg[v];
        dinv[v] = (d > 0) ? rsqrtf((float)d) : 0.0f;
        diag[v] = (d > 0) ? 0.0f : -1.0f;
    }
}

__global__ void k_scan(const int* __restrict__ deg, int* __restrict__ off,
                       int* __restrict__ cursor) {
    __shared__ int sh[1024];
    __shared__ int carry;
    int t = threadIdx.x;
    if (t == 0) carry = 0;
    __syncthreads();
    for (int base = 0; base < NNODES; base += 1024) {
        int i = base + t;
        int v = (i < NNODES) ? deg[i] : 0;
        sh[t] = v;
        __syncthreads();
        for (int ofs = 1; ofs < 1024; ofs <<= 1) {
            int x = (t >= ofs) ? sh[t - ofs] : 0;
            __syncthreads();
            sh[t] += x;
            __syncthreads();
        }
        int excl = carry + sh[t] - v;
        if (i < NNODES) { off[i] = excl; cursor[i] = excl; }
        __syncthreads();
        if (t == 1023) carry += sh[1023];
        __syncthreads();
    }
    if (t == 0) off[NNODES] = carry;
}

__global__ void k_csr(const int* __restrict__ row, const int* __restrict__ col,
                      const float* __restrict__ dinv, int* __restrict__ cursor,
                      int* __restrict__ ccol, float* __restrict__ cw) {
    int e = blockIdx.x * blockDim.x + threadIdx.x;
    if (e < NEDGES) {
        int r = row[e], c = col[e];
        int pos = atomicAdd(&cursor[r], 1);
        ccol[pos] = c;
        cw[pos] = -dinv[r] * dinv[c];
    }
}

// ---------------- Lhat aggregation (float2-vectorized CSR gather) -------------
// Correctness proven R16 (bitwise-identical per-feature accumulation vs R14).
// mode 0: out = agg(h) + diag*h
// mode 1: out = 2*(agg(h) + diag*h) - t0
__global__ void k_lhat2(const float2* __restrict__ h, const float2* __restrict__ t0,
                        const int* __restrict__ off, const int* __restrict__ ccol,
                        const float* __restrict__ cw, const float* __restrict__ diag,
                        float2* __restrict__ out, int F2, int mode) {
    int v = blockIdx.x;
    int f = blockIdx.y * blockDim.x + threadIdx.x;
    if (f >= F2) return;
    int e0 = off[v], e1 = off[v + 1];
    float ax = 0.0f, ay = 0.0f;
    int e = e0;
    for (; e + 4 <= e1; e += 4) {
        int c0 = ccol[e + 0], c1 = ccol[e + 1], c2 = ccol[e + 2], c3 = ccol[e + 3];
        float w0 = cw[e + 0], w1 = cw[e + 1], w2 = cw[e + 2], w3 = cw[e + 3];
        float2 h0 = h[(size_t)c0 * F2 + f];
        float2 h1 = h[(size_t)c1 * F2 + f];
        float2 h2 = h[(size_t)c2 * F2 + f];
        float2 h3 = h[(size_t)c3 * F2 + f];
        ax += w0 * h0.x + w1 * h1.x + w2 * h2.x + w3 * h3.x;
        ay += w0 * h0.y + w1 * h1.y + w2 * h2.y + w3 * h3.y;
    }
    for (; e < e1; ++e) {
        int c = ccol[e];
        float w = cw[e];
        float2 hv = h[(size_t)c * F2 + f];
        ax += w * hv.x;
        ay += w * hv.y;
    }
    float dg = diag[v];
    float2 hv = h[(size_t)v * F2 + f];
    ax += dg * hv.x;
    ay += dg * hv.y;
    if (mode) {
        float2 tv = t0[(size_t)v * F2 + f];
        ax = 2.0f * ax - tv.x;
        ay = 2.0f * ay - tv.y;
    }
    out[(size_t)v * F2 + f] = make_float2(ax, ay);
}

// ---------------- fused 3-term GEMM + bias + relu (proven R14) ----------------
// out[M,N] = relu(T0@W[0] + T1@W[1] + T2@W[2] + bias),  W is [3,K,N] row-major
#define BM 128
#define BN 128
#define BKK 8
#define TM 8
#define TN 8

__global__ __launch_bounds__(256) void k_gemm3(
    const float* __restrict__ A0, const float* __restrict__ A1,
    const float* __restrict__ A2, const float* __restrict__ W,
    const float* __restrict__ bias, float* __restrict__ out,
    int M, int N, int K) {
    __shared__ float As[BKK][BM];
    __shared__ float Bs[BKK][BN];
    int bm = blockIdx.y * BM, bn = blockIdx.x * BN;
    int t = threadIdx.x;
    int tx = t & 15, ty = t >> 4;      // 16x16 thread grid
    float acc[TM][TN];
#pragma unroll
    for (int i = 0; i < TM; i++)
#pragma unroll
        for (int j = 0; j < TN; j++) acc[i][j] = 0.0f;

    const float* Aptr[3] = {A0, A1, A2};
    for (int kk = 0; kk < 3; ++kk) {
        const float* A = Aptr[kk];
        const float* B = W + (size_t)kk * K * N;
        for (int k0 = 0; k0 < K; k0 += BKK) {
            // load A tile 128x8 (store transposed)
#pragma unroll
            for (int i = 0; i < 4; i++) {
                int idx = i * 256 + t;
                int m = idx >> 3, kc = idx & 7;
                int gm = bm + m, gk = k0 + kc;
                As[kc][m] = (gm < M && gk < K) ? A[(size_t)gm * K + gk] : 0.0f;
            }
            // load B tile 8x128 (coalesced along N)
#pragma unroll
            for (int i = 0; i < 4; i++) {
                int idx = i * 256 + t;
                int kc = idx >> 7, n = idx & 127;
                int gk = k0 + kc, gn = bn + n;
                Bs[kc][n] = (gk < K && gn < N) ? B[(size_t)gk * N + gn] : 0.0f;
            }
            __syncthreads();
#pragma unroll
            for (int kb = 0; kb < BKK; kb++) {
                float a[TM], b[TN];
                float4 a0 = *reinterpret_cast<const float4*>(&As[kb][ty * TM]);
                float4 a1 = *reinterpret_cast<const float4*>(&As[kb][ty * TM + 4]);
                float4 b0 = *reinterpret_cast<const float4*>(&Bs[kb][tx * TN]);
                float4 b1 = *reinterpret_cast<const float4*>(&Bs[kb][tx * TN + 4]);
                a[0] = a0.x; a[1] = a0.y; a[2] = a0.z; a[3] = a0.w;
                a[4] = a1.x; a[5] = a1.y; a[6] = a1.z; a[7] = a1.w;
                b[0] = b0.x; b[1] = b0.y; b[2] = b0.z; b[3] = b0.w;
                b[4] = b1.x; b[5] = b1.y; b[6] = b1.z; b[7] = b1.w;
#pragma unroll
                for (int i = 0; i < TM; i++)
#pragma unroll
                    for (int j = 0; j < TN; j++) acc[i][j] += a[i] * b[j];
            }
            __syncthreads();
        }
    }
#pragma unroll
    for (int i = 0; i < TM; i++) {
        int gm = bm + ty * TM + i;
        if (gm >= M) continue;
#pragma unroll
        for (int j = 0; j < TN; j++) {
            int gn = bn + tx * TN + j;
            if (gn < N) {
                float v = acc[i][j] + bias[gn];
                out[(size_t)gm * N + gn] = fmaxf(v, 0.0f);
            }
        }
    }
}

// ---------------- launch ------------------------------------------------------
static inline int cdiv(int a, int b) { return (a + b - 1) / b; }

extern "C" void kernel_launch(void* const* d_in, const int* in_sizes, int n_in,
                              void* d_out, int out_size) {
    const float* x  = (const float*)d_in[0];
    const void*  ei = d_in[1];               // int32 or int64 — detected on device
    const float* w1 = (const float*)d_in[2];
    const float* b1 = (const float*)d_in[3];
    const float* w2 = (const float*)d_in[4];
    const float* b2 = (const float*)d_in[5];
    const float* w3 = (const float*)d_in[6];
    const float* b3 = (const float*)d_in[7];
    float* out = (float*)d_out;

    float *T1, *T2, *h1, *h2, *dinv, *diag, *cw;
    int *row, *col, *deg, *off, *cursor, *ccol;
    cudaGetSymbolAddress((void**)&T1, g_T1);
    cudaGetSymbolAddress((void**)&T2, g_T2);
    cudaGetSymbolAddress((void**)&h1, g_h1);
    cudaGetSymbolAddress((void**)&h2, g_h2);
    cudaGetSymbolAddress((void**)&row, g_row);
    cudaGetSymbolAddress((void**)&col, g_col);
    cudaGetSymbolAddress((void**)&deg, g_deg);
    cudaGetSymbolAddress((void**)&dinv, g_dinv);
    cudaGetSymbolAddress((void**)&diag, g_diag);
    cudaGetSymbolAddress((void**)&off, g_off);
    cudaGetSymbolAddress((void**)&cursor, g_cursor);
    cudaGetSymbolAddress((void**)&ccol, g_ccol);
    cudaGetSymbolAddress((void**)&cw, g_cw);

    const int M = NNODES;

    // ---- preprocessing (verified R14) ----
    k_zero<<<cdiv(NNODES, 256), 256>>>(deg, NNODES);
    k_detect<<<1, 32>>>((const long long*)ei);
    k_deg<<<cdiv(NEDGES, 256), 256>>>(ei, row, col, deg);
    k_dinv<<<cdiv(NNODES, 256), 256>>>(deg, dinv, diag);
    k_scan<<<1, 1024>>>(deg, off, cursor);
    k_csr<<<cdiv(NEDGES, 256), 256>>>(row, col, dinv, cursor, ccol, cw);

    // ---- layer 1: F=512 -> 250 ----
    {
        int F = 512, N = 250, K = 512, F2 = F / 2;
        dim3 lg(M, cdiv(F2, 128));
        k_lhat2<<<lg, 128>>>((const float2*)x, nullptr, off, ccol, cw, diag,
                             (float2*)T1, F2, 0);
        k_lhat2<<<lg, 128>>>((const float2*)T1, (const float2*)x, off, ccol, cw, diag,
                             (float2*)T2, F2, 1);
        dim3 gg(cdiv(N, BN), cdiv(M, BM));
        k_gemm3<<<gg, 256>>>(x, T1, T2, w1, b1, h1, M, N, K);
    }
    // ---- layer 2: F=250 -> 500 ----
    {
        int F = 250, N = 500, K = 250, F2 = F / 2;
        dim3 lg(M, cdiv(F2, 128));
        k_lhat2<<<lg, 128>>>((const float2*)h1, nullptr, off, ccol, cw, diag,
                             (float2*)T1, F2, 0);
        k_lhat2<<<lg, 128>>>((const float2*)T1, (const float2*)h1, off, ccol, cw, diag,
                             (float2*)T2, F2, 1);
        dim3 gg(cdiv(N, BN), cdiv(M, BM));
        k_gemm3<<<gg, 256>>>(h1, T1, T2, w2, b2, h2, M, N, K);
    }
    // ---- layer 3: F=500 -> 1000 ----
    {
        int F = 500, N = 1000, K = 500, F2 = F / 2;
        dim3 lg(M, cdiv(F2, 128));
        k_lhat2<<<lg, 128>>>((const float2*)h2, nullptr, off, ccol, cw, diag,
                             (float2*)T1, F2, 0);
        k_lhat2<<<lg, 128>>>((const float2*)T1, (const float2*)h2, off, ccol, cw, diag,
                             (float2*)T2, F2, 1);
        dim3 gg(cdiv(N, BN), cdiv(M, BM));
        k_gemm3<<<gg, 256>>>(h2, T1, T2, w3, b3, out, M, N, K);
    }
}